// round 15
// baseline (speedup 1.0000x reference)
#include <cuda_runtime.h>
#include <stdint.h>

// RadialTokenizer — pair-gather (LDG.64, 2 px/instruction) + exact singles.
// bin = floor((x*0.5+0.5)*255)-127 in [0,127]; 16 rings: mean/std/median
// from exact per-ring 128-bin histograms.
// Ring row-spans are enumerated analytically; even-aligned pairs fully
// inside a span go to the pair list (one float2 load each), boundary px to
// a singles list. Warp = ring pair (p, 15-p): identical work. Per-lane byte
// histograms (bank==lane, conflict-free, no atomics).

#define HH 256
#define WW 256
#define NR 16
#define PSTRIDE 4096    // pairs per ring (max ~3.1K)
#define SSTRIDE 2048    // singles per ring (max ~1.1K)

__device__ int g_pcur[NR];     // zero-init at load; reset by ticket each run
__device__ int g_scur[NR];
__device__ int g_ticket;
__device__ int g_np[NR];
__device__ int g_ns[NR];
__device__ __align__(128) uint16_t g_pair[NR * PSTRIDE];
__device__ __align__(128) uint16_t g_sing[NR * SSTRIDE];

__device__ __forceinline__ int isqrt_i(int v) {
    int s = (int)sqrtf((float)v);
    while (s > 0 && s * s > v) s--;
    while ((s + 1) * (s + 1) <= v) s++;
    return s;
}

// ---------------- init kernel: block = row, lane = (ring, side) ----------------
// ring r <=> 64r^2 < d2 <= 64(r+1)^2, d2 > 0.
// Right span dx in [max(wi,1), wo]; left span dx in [-wo, -wiL],
// wiL = wi except (wi==0 && dy==0) -> 1 (excludes center px, no dbl-count of dx=0).

__global__ void k_build() {
    const int y    = blockIdx.x;
    const int lane = threadIdx.x;
    const int r    = lane >> 1;
    const int side = lane & 1;
    const int dy   = y - 128;
    const int dy2  = dy * dy;

    int Ro2 = 64 * (r + 1) * (r + 1) - dy2;
    if (Ro2 >= 0) {
        int wo = isqrt_i(Ro2);
        int Ri2 = 64 * r * r - dy2;
        int wi = (Ri2 < 0) ? 0 : (isqrt_i(Ri2) + 1);
        int xa, xb;
        if (side == 0) {                       // left
            int wiL = (wi == 0 && dy == 0) ? 1 : wi;
            xa = 128 - wo; xb = 128 - wiL;
        } else {                               // right
            int wiR = (wi > 1) ? wi : 1;
            xa = 128 + wiR; xb = 128 + wo;
        }
        if (xb >= xa) {
            int kmin = (xa + 1) >> 1;
            int kmax = (xb - 1) >> 1;
            int npairs = kmax - kmin + 1;
            if (npairs > 0) {
                int pos = atomicAdd(&g_pcur[r], npairs);
                for (int k = kmin; k <= kmax; k++)
                    g_pair[r * PSTRIDE + pos++] = (uint16_t)((y << 7) | k);
            }
            int ns = 0;
            uint16_t s0 = 0, s1 = 0;
            if (xa & 1)  { s0 = (uint16_t)((y << 8) | xa); ns = 1; }
            if (!(xb & 1)) { s1 = (uint16_t)((y << 8) | xb); ns++; }
            if (ns) {
                int pos = atomicAdd(&g_scur[r], ns);
                if (xa & 1) g_sing[r * SSTRIDE + pos++] = s0;
                if (!(xb & 1)) g_sing[r * SSTRIDE + pos] = s1;
            }
        }
    }
    __syncwarp();
    if (lane == 0) {
        __threadfence();
        int t = atomicAdd(&g_ticket, 1);
        if (t == 255) {                        // last block: publish + reset
            __threadfence();
            for (int i = 0; i < NR; i++) {
                g_np[i] = atomicAdd(&g_pcur[i], 0);
                g_ns[i] = atomicAdd(&g_scur[i], 0);
            }
            for (int i = 0; i < NR; i++) { g_pcur[i] = 0; g_scur[i] = 0; }
            g_ticket = 0;
            __threadfence();
        }
    }
}

// ---------------- main kernel ----------------
// Grid 1536 = (bc=768) x 2 halves; block 128 (4 warps, 16KB smem).
// Warp w -> rings p, 15-p with p = (bx&1)*4 + w.
// Hist byte addr = ((bin<<5)&0xF80) | (lane<<2) | (bin&3)  -> bank == lane.

__global__ void __launch_bounds__(128, 8) k_main(const float* __restrict__ img,
                                                 float* __restrict__ out) {
    __shared__ uint8_t hist[4][4096];

    const int lane = threadIdx.x & 31;
    const int w    = threadIdx.x >> 5;
    const int bc   = blockIdx.x >> 1;
    const int p    = ((blockIdx.x & 1) << 2) + w;

    uint8_t* h = hist[w];
    const float*  __restrict__ ip  = img + (size_t)bc * (HH * WW);
    const float2* __restrict__ ip2 = (const float2*)ip;
    const int hb_lane = lane << 2;
    const int b = bc / 3, c = bc - b * 3;

    #pragma unroll
    for (int rr = 0; rr < 2; rr++) {
        const int ring = rr ? (15 - p) : p;

        // zero this warp's 4KB histogram
        {
            uint4* hz = (uint4*)h;
            uint4 z; z.x = z.y = z.z = z.w = 0u;
            #pragma unroll
            for (int j = 0; j < 8; j++) hz[j * 32 + lane] = z;
        }
        __syncwarp();

        const int npair = g_np[ring];
        const int nsing = g_ns[ring];
        const int n = npair * 2 + nsing;
        const uint16_t* __restrict__ plist = g_pair + ring * PSTRIDE;
        const uint32_t* __restrict__ p32   = (const uint32_t*)plist;
        const uint16_t* __restrict__ slist = g_sing + ring * SSTRIDE;

        // ---- pairs main loop: 128 pairs (256 px)/step, pipelined offsets ----
        const int nfullp = npair & ~127;
        uint32_t ow[2];
        #pragma unroll
        for (int j = 0; j < 2; j++)
            ow[j] = (nfullp > 0) ? p32[j * 32 + lane] : 0u;

        for (int base = 0; base < nfullp; base += 128) {
            float2 v0 = __ldcs(ip2 + (ow[0] & 0xFFFFu));
            float2 v1 = __ldcs(ip2 + (ow[0] >> 16));
            float2 v2 = __ldcs(ip2 + (ow[1] & 0xFFFFu));
            float2 v3 = __ldcs(ip2 + (ow[1] >> 16));
            uint32_t nw0 = 0, nw1 = 0;
            const int nb = base + 128;
            if (nb < nfullp) {
                nw0 = p32[(nb >> 1) + lane];
                nw1 = p32[(nb >> 1) + 32 + lane];
            }
            float xv[8] = {v0.x, v0.y, v1.x, v1.y, v2.x, v2.y, v3.x, v3.y};
            #pragma unroll
            for (int j = 0; j < 8; j++) {
                // bit-identical to ref: fma(x,0.5,0.5) (exact mul -> single
                // rounding == (x*0.5)+0.5), unfused *255, floor.
                float t = __fmul_rn(__fmaf_rn(xv[j], 0.5f, 0.5f), 255.0f);
                int bin = __float2int_rd(t) - 127;
                h[((bin << 5) & 0xF80) | hb_lane | (bin & 3)] += 1;
            }
            ow[0] = nw0; ow[1] = nw1;
        }
        // pair tail (< 128 pairs)
        for (int i = nfullp + lane; i < npair; i += 32) {
            float2 q = __ldcs(ip2 + plist[i]);
            float t0 = __fmul_rn(__fmaf_rn(q.x, 0.5f, 0.5f), 255.0f);
            float t1 = __fmul_rn(__fmaf_rn(q.y, 0.5f, 0.5f), 255.0f);
            int b0_ = __float2int_rd(t0) - 127;
            int b1_ = __float2int_rd(t1) - 127;
            h[((b0_ << 5) & 0xF80) | hb_lane | (b0_ & 3)] += 1;
            h[((b1_ << 5) & 0xF80) | hb_lane | (b1_ & 3)] += 1;
        }
        // singles
        for (int i = lane; i < nsing; i += 32) {
            float t = __fmul_rn(__fmaf_rn(__ldcs(ip + slist[i]), 0.5f, 0.5f), 255.0f);
            int bin = __float2int_rd(t) - 127;
            h[((bin << 5) & 0xF80) | hb_lane | (bin & 3)] += 1;
        }
        __syncwarp();

        // ---- reduce: lane l owns bins 4l..4l+3 ----
        const uint32_t* hw = (const uint32_t*)h;
        uint32_t a02 = 0, a13 = 0;
        #pragma unroll
        for (int jj = 0; jj < 32; jj++) {
            int j = (jj + lane) & 31;
            uint32_t vv = hw[lane * 32 + j];
            a02 += vv & 0x00FF00FFu;
            a13 += (vv >> 8) & 0x00FF00FFu;
        }
        int h0 = (int)(a02 & 0xFFFFu), h2 = (int)(a02 >> 16);
        int h1 = (int)(a13 & 0xFFFFu), h3 = (int)(a13 >> 16);

        const int b0 = lane * 4;
        int sl  = h0 + h1 + h2 + h3;
        int sb  = h0 * b0 + h1 * (b0 + 1) + h2 * (b0 + 2) + h3 * (b0 + 3);
        int sb2 = h0 * b0 * b0 + h1 * (b0 + 1) * (b0 + 1)
                + h2 * (b0 + 2) * (b0 + 2) + h3 * (b0 + 3) * (b0 + 3);

        int sumb  = __reduce_add_sync(0xffffffffu, sb);
        int sumb2 = __reduce_add_sync(0xffffffffu, sb2);

        int sc = sl;
        #pragma unroll
        for (int d = 1; d < 32; d <<= 1) {
            int t2 = __shfl_up_sync(0xffffffffu, sc, d);
            if (lane >= d) sc += t2;
        }
        int cb = sc - sl;

        int k1 = (n - 1) >> 1, k2 = n >> 1;
        int c1 = 1 << 30, c2 = 1 << 30;
        {
            int t1 = k1 + 1;
            if (cb < t1 && t1 <= sc) {
                if      (cb + h0 >= t1)           c1 = b0;
                else if (cb + h0 + h1 >= t1)      c1 = b0 + 1;
                else if (cb + h0 + h1 + h2 >= t1) c1 = b0 + 2;
                else                              c1 = b0 + 3;
            }
            int t2r = k2 + 1;
            if (cb < t2r && t2r <= sc) {
                if      (cb + h0 >= t2r)           c2 = b0;
                else if (cb + h0 + h1 >= t2r)      c2 = b0 + 1;
                else if (cb + h0 + h1 + h2 >= t2r) c2 = b0 + 2;
                else                               c2 = b0 + 3;
            }
        }
        int m1 = __reduce_min_sync(0xffffffffu, c1);
        int m2 = __reduce_min_sync(0xffffffffu, c2);

        if (lane == 0) {
            double dn = (double)n;
            double mb = (double)sumb / dn;
            double mean = 127.0 + mb;
            double var = (double)sumb2 / dn - mb * mb;
            double sd = sqrt(var > 0.0 ? var : 0.0);
            double med = 127.0 + 0.5 * (double)(m1 + m2);
            int o = b * (NR * 9) + ring * 9 + c;
            out[o]     = (float)mean;
            out[o + 3] = (float)sd;
            out[o + 6] = (float)med;
        }
        __syncwarp();
    }
}

extern "C" void kernel_launch(void* const* d_in, const int* in_sizes, int n_in,
                              void* d_out, int out_size) {
    const float* img = (const float*)d_in[0];
    float* out = (float*)d_out;

    k_build<<<HH, 32>>>();
    k_main<<<1536, 128>>>(img, out);
}

// round 16
// speedup vs baseline: 1.0638x; 1.0638x over previous
#include <cuda_runtime.h>
#include <stdint.h>

// RadialTokenizer — direct gather (R14 structure) + analytic one-launch init.
// bin = floor((x*0.5+0.5)*255)-127 in [0,127]; 16 rings: mean/std/median
// from exact per-ring 128-bin histograms.
// Warp = ring pair (p, 15-p): identical work per warp. Per-lane byte
// histograms (bank==lane, conflict-free, no atomics). Offset loads for the
// next 256-px step are prefetched while the current gathers are in flight.

#define HH 256
#define WW 256
#define NR 16
#define RSTRIDE 8192     // slots per ring; max ring population ~6232

__device__ int g_cur[NR];      // cursors: zero at load; ticket-reset each run
__device__ int g_ticket;
__device__ int g_n[NR];        // published ring counts
__device__ __align__(128) uint16_t g_list[NR * RSTRIDE];

__device__ __forceinline__ int isqrt_i(int v) {
    int s = (int)sqrtf((float)v);
    while (s > 0 && s * s > v) s--;
    while ((s + 1) * (s + 1) <= v) s++;
    return s;
}

// ---------------- init kernel: <<<256, 32>>>, block = row, lane = (ring, side)
// ring r <=> 64r^2 < d2 <= 64(r+1)^2 (d2 > 0). Right span dx in
// [max(wi,1), wo] clamped to x<=255; left span dx in [-wo, -wiL], where
// wiL = wi except (wi==0 && dy==0) -> 1 (excludes center, no dx=0 dbl-count).

__global__ void k_build() {
    const int y    = blockIdx.x;
    const int lane = threadIdx.x;
    const int r    = lane >> 1;
    const int side = lane & 1;
    const int dy   = y - 128;
    const int dy2  = dy * dy;

    int xa = 0, xb = -1;
    int Ro2 = 64 * (r + 1) * (r + 1) - dy2;
    if (Ro2 >= 0) {
        int wo  = isqrt_i(Ro2);
        int Ri2 = 64 * r * r - dy2;
        int wi  = (Ri2 < 0) ? 0 : (isqrt_i(Ri2) + 1);
        if (side == 0) {                         // left (includes dx=0)
            int wiL = (wi == 0 && dy == 0) ? 1 : wi;
            xa = 128 - wo; xb = 128 - wiL;
        } else {                                 // right (dx >= 1)
            int wiR = (wi > 1) ? wi : 1;
            xa = 128 + wiR; xb = 128 + wo;
            if (xb > 255) xb = 255;              // grid bound (y=128,r=15 case)
        }
    }
    int len = xb - xa + 1;
    if (len < 0) len = 0;
    int pos = len ? atomicAdd(&g_cur[r], len) : 0;
    for (int x = xa; x <= xb; x++)
        g_list[r * RSTRIDE + pos++] = (uint16_t)((y << 8) | x);

    __syncwarp();
    if (lane == 0) {
        __threadfence();
        int t = atomicAdd(&g_ticket, 1);
        if (t == HH - 1) {                       // last row: publish + reset
            __threadfence();
            for (int i = 0; i < NR; i++) g_n[i] = atomicAdd(&g_cur[i], 0);
            for (int i = 0; i < NR; i++) g_cur[i] = 0;
            g_ticket = 0;
            __threadfence();
        }
    }
}

// ---------------- main kernel ----------------
// Grid 1536 = (bc=768) x 2 halves; block 128 (4 warps, 16KB smem,
// 10 blocks/SM -> 40 warps/SM). Warp w -> rings p, 15-p with p=(bx&1)*4+w.
// Hist byte addr = ((bin<<5)&0xF80) | (lane<<2) | (bin&3)  -> bank == lane.

__global__ void __launch_bounds__(128, 10) k_main(const float* __restrict__ img,
                                                  float* __restrict__ out) {
    __shared__ uint8_t hist[4][4096];

    const int lane = threadIdx.x & 31;
    const int w    = threadIdx.x >> 5;
    const int bc   = blockIdx.x >> 1;
    const int p    = ((blockIdx.x & 1) << 2) + w;

    uint8_t* h = hist[w];
    const float* __restrict__ ip = img + (size_t)bc * (HH * WW);
    const int hb_lane = lane << 2;
    const int b = bc / 3, c = bc - b * 3;

    #pragma unroll
    for (int rr = 0; rr < 2; rr++) {
        const int ring = rr ? (15 - p) : p;

        // zero this warp's 4KB histogram
        {
            uint4* hz = (uint4*)h;
            uint4 z; z.x = z.y = z.z = z.w = 0u;
            #pragma unroll
            for (int j = 0; j < 8; j++) hz[j * 32 + lane] = z;
        }
        __syncwarp();

        const int n = g_n[ring];
        const uint16_t* __restrict__ offs = g_list + ring * RSTRIDE;
        const uint32_t* __restrict__ o32 = (const uint32_t*)offs;

        // pipelined main loop: 256 px/step, 8 independent gathers in flight,
        // next step's packed offsets prefetched during current gathers.
        const int nfull = n & ~255;
        uint32_t ow[4];
        #pragma unroll
        for (int j = 0; j < 4; j++)
            ow[j] = (nfull > 0) ? o32[j * 32 + lane] : 0u;

        for (int base = 0; base < nfull; base += 256) {
            float v[8];
            #pragma unroll
            for (int j = 0; j < 4; j++) {
                v[2 * j]     = __ldcs(ip + (ow[j] & 0xFFFFu));
                v[2 * j + 1] = __ldcs(ip + (ow[j] >> 16));
            }
            uint32_t nw[4];
            const int nb = base + 256;
            #pragma unroll
            for (int j = 0; j < 4; j++)
                nw[j] = (nb < nfull) ? o32[(nb >> 1) + j * 32 + lane] : 0u;
            #pragma unroll
            for (int j = 0; j < 8; j++) {
                // bit-identical to ref: fma(x,0.5,0.5) (exact mul -> single
                // rounding == (x*0.5)+0.5), then unfused *255, then floor.
                float t = __fmul_rn(__fmaf_rn(v[j], 0.5f, 0.5f), 255.0f);
                int bin = __float2int_rd(t) - 127;
                h[((bin << 5) & 0xF80) | hb_lane | (bin & 3)] += 1;
            }
            #pragma unroll
            for (int j = 0; j < 4; j++) ow[j] = nw[j];
        }
        // tail (< 256 px)
        for (int i = nfull + lane; i < n; i += 32) {
            int off = offs[i];
            float t = __fmul_rn(__fmaf_rn(__ldcs(ip + off), 0.5f, 0.5f), 255.0f);
            int bin = __float2int_rd(t) - 127;
            h[((bin << 5) & 0xF80) | hb_lane | (bin & 3)] += 1;
        }
        __syncwarp();

        // ---- reduce: lane l owns bins 4l..4l+3; sum byte cols of 32 lanes ----
        const uint32_t* hw = (const uint32_t*)h;
        uint32_t a02 = 0, a13 = 0;
        #pragma unroll
        for (int jj = 0; jj < 32; jj++) {
            int j = (jj + lane) & 31;
            uint32_t vv = hw[lane * 32 + j];
            a02 += vv & 0x00FF00FFu;
            a13 += (vv >> 8) & 0x00FF00FFu;
        }
        int h0 = (int)(a02 & 0xFFFFu), h2 = (int)(a02 >> 16);
        int h1 = (int)(a13 & 0xFFFFu), h3 = (int)(a13 >> 16);

        const int b0 = lane * 4;
        int sl  = h0 + h1 + h2 + h3;
        int sb  = h0 * b0 + h1 * (b0 + 1) + h2 * (b0 + 2) + h3 * (b0 + 3);
        int sb2 = h0 * b0 * b0 + h1 * (b0 + 1) * (b0 + 1)
                + h2 * (b0 + 2) * (b0 + 2) + h3 * (b0 + 3) * (b0 + 3);

        int sumb  = __reduce_add_sync(0xffffffffu, sb);
        int sumb2 = __reduce_add_sync(0xffffffffu, sb2);

        int sc = sl;
        #pragma unroll
        for (int d = 1; d < 32; d <<= 1) {
            int t2 = __shfl_up_sync(0xffffffffu, sc, d);
            if (lane >= d) sc += t2;
        }
        int cb = sc - sl;

        int k1 = (n - 1) >> 1, k2 = n >> 1;
        int c1 = 1 << 30, c2 = 1 << 30;
        {
            int t1 = k1 + 1;
            if (cb < t1 && t1 <= sc) {
                if      (cb + h0 >= t1)           c1 = b0;
                else if (cb + h0 + h1 >= t1)      c1 = b0 + 1;
                else if (cb + h0 + h1 + h2 >= t1) c1 = b0 + 2;
                else                              c1 = b0 + 3;
            }
            int t2r = k2 + 1;
            if (cb < t2r && t2r <= sc) {
                if      (cb + h0 >= t2r)           c2 = b0;
                else if (cb + h0 + h1 >= t2r)      c2 = b0 + 1;
                else if (cb + h0 + h1 + h2 >= t2r) c2 = b0 + 2;
                else                               c2 = b0 + 3;
            }
        }
        int m1 = __reduce_min_sync(0xffffffffu, c1);
        int m2 = __reduce_min_sync(0xffffffffu, c2);

        if (lane == 0) {
            double dn = (double)n;
            double mb = (double)sumb / dn;
            double mean = 127.0 + mb;
            double var = (double)sumb2 / dn - mb * mb;
            double sd = sqrt(var > 0.0 ? var : 0.0);
            double med = 127.0 + 0.5 * (double)(m1 + m2);
            int o = b * (NR * 9) + ring * 9 + c;
            out[o]     = (float)mean;
            out[o + 3] = (float)sd;
            out[o + 6] = (float)med;
        }
        __syncwarp();
    }
}

extern "C" void kernel_launch(void* const* d_in, const int* in_sizes, int n_in,
                              void* d_out, int out_size) {
    const float* img = (const float*)d_in[0];
    float* out = (float*)d_out;

    k_build<<<HH, 32>>>();
    k_main<<<1536, 128>>>(img, out);
}

// round 17
// speedup vs baseline: 1.2297x; 1.1560x over previous
#include <cuda_runtime.h>
#include <stdint.h>

// RadialTokenizer — direct gather (R14-proven main kernel, 64-reg pipeline)
// + analytic one-launch init (R16-proven).
// bin = floor((x*0.5+0.5)*255)-127 in [0,127]; 16 rings: mean/std/median
// from exact per-ring 128-bin histograms.
// Warp = ring pair (p, 15-p): identical work per warp. Per-lane byte
// histograms (bank==lane, conflict-free, no atomics). Offset loads for the
// next 256-px step are prefetched while the current gathers are in flight.

#define HH 256
#define WW 256
#define NR 16
#define RSTRIDE 8192     // slots per ring; max ring population ~6232

__device__ int g_cur[NR];      // cursors: zero at load; ticket-reset each run
__device__ int g_ticket;
__device__ int g_n[NR];        // published ring counts
__device__ __align__(128) uint16_t g_list[NR * RSTRIDE];

__device__ __forceinline__ int isqrt_i(int v) {
    int s = (int)sqrtf((float)v);
    while (s > 0 && s * s > v) s--;
    while ((s + 1) * (s + 1) <= v) s++;
    return s;
}

// ---------------- init kernel: <<<256, 32>>>, block = row, lane = (ring, side)
// ring r <=> 64r^2 < d2 <= 64(r+1)^2 (d2 > 0). Right span dx in
// [max(wi,1), wo] clamped to x<=255; left span dx in [-wo, -wiL], where
// wiL = wi except (wi==0 && dy==0) -> 1 (excludes center, no dx=0 dbl-count).

__global__ void k_build() {
    const int y    = blockIdx.x;
    const int lane = threadIdx.x;
    const int r    = lane >> 1;
    const int side = lane & 1;
    const int dy   = y - 128;
    const int dy2  = dy * dy;

    int xa = 0, xb = -1;
    int Ro2 = 64 * (r + 1) * (r + 1) - dy2;
    if (Ro2 >= 0) {
        int wo  = isqrt_i(Ro2);
        int Ri2 = 64 * r * r - dy2;
        int wi  = (Ri2 < 0) ? 0 : (isqrt_i(Ri2) + 1);
        if (side == 0) {                         // left (includes dx=0)
            int wiL = (wi == 0 && dy == 0) ? 1 : wi;
            xa = 128 - wo; xb = 128 - wiL;
        } else {                                 // right (dx >= 1)
            int wiR = (wi > 1) ? wi : 1;
            xa = 128 + wiR; xb = 128 + wo;
            if (xb > 255) xb = 255;              // grid bound (y=128,r=15 case)
        }
    }
    int len = xb - xa + 1;
    if (len < 0) len = 0;
    int pos = len ? atomicAdd(&g_cur[r], len) : 0;
    for (int x = xa; x <= xb; x++)
        g_list[r * RSTRIDE + pos++] = (uint16_t)((y << 8) | x);

    __syncwarp();
    if (lane == 0) {
        __threadfence();
        int t = atomicAdd(&g_ticket, 1);
        if (t == HH - 1) {                       // last row: publish + reset
            __threadfence();
            for (int i = 0; i < NR; i++) g_n[i] = atomicAdd(&g_cur[i], 0);
            for (int i = 0; i < NR; i++) g_cur[i] = 0;
            g_ticket = 0;
            __threadfence();
        }
    }
}

// ---------------- main kernel ----------------
// Grid 1536 = (bc=768) x 2 halves; block 128 (4 warps, 16KB smem,
// 8 blocks/SM -> regs 64, no spills). Warp w -> rings p, 15-p, p=(bx&1)*4+w.
// Hist byte addr = ((bin<<5)&0xF80) | (lane<<2) | (bin&3)  -> bank == lane.

__global__ void __launch_bounds__(128, 8) k_main(const float* __restrict__ img,
                                                 float* __restrict__ out) {
    __shared__ uint8_t hist[4][4096];

    const int lane = threadIdx.x & 31;
    const int w    = threadIdx.x >> 5;
    const int bc   = blockIdx.x >> 1;
    const int p    = ((blockIdx.x & 1) << 2) + w;

    uint8_t* h = hist[w];
    const float* __restrict__ ip = img + (size_t)bc * (HH * WW);
    const int hb_lane = lane << 2;
    const int b = bc / 3, c = bc - b * 3;

    #pragma unroll
    for (int rr = 0; rr < 2; rr++) {
        const int ring = rr ? (15 - p) : p;

        // zero this warp's 4KB histogram
        {
            uint4* hz = (uint4*)h;
            uint4 z; z.x = z.y = z.z = z.w = 0u;
            #pragma unroll
            for (int j = 0; j < 8; j++) hz[j * 32 + lane] = z;
        }
        __syncwarp();

        const int n = g_n[ring];
        const uint16_t* __restrict__ offs = g_list + ring * RSTRIDE;
        const uint32_t* __restrict__ o32 = (const uint32_t*)offs;

        // pipelined main loop: 256 px/step, 8 independent gathers in flight,
        // next step's packed offsets prefetched during current gathers.
        const int nfull = n & ~255;
        uint32_t ow[4];
        #pragma unroll
        for (int j = 0; j < 4; j++)
            ow[j] = (nfull > 0) ? o32[j * 32 + lane] : 0u;

        for (int base = 0; base < nfull; base += 256) {
            float v[8];
            #pragma unroll
            for (int j = 0; j < 4; j++) {
                v[2 * j]     = __ldcs(ip + (ow[j] & 0xFFFFu));
                v[2 * j + 1] = __ldcs(ip + (ow[j] >> 16));
            }
            uint32_t nw[4];
            const int nb = base + 256;
            #pragma unroll
            for (int j = 0; j < 4; j++)
                nw[j] = (nb < nfull) ? o32[(nb >> 1) + j * 32 + lane] : 0u;
            #pragma unroll
            for (int j = 0; j < 8; j++) {
                // bit-identical to ref: fma(x,0.5,0.5) (exact mul -> single
                // rounding == (x*0.5)+0.5), then unfused *255, then floor.
                float t = __fmul_rn(__fmaf_rn(v[j], 0.5f, 0.5f), 255.0f);
                int bin = __float2int_rd(t) - 127;
                h[((bin << 5) & 0xF80) | hb_lane | (bin & 3)] += 1;
            }
            #pragma unroll
            for (int j = 0; j < 4; j++) ow[j] = nw[j];
        }
        // tail (< 256 px)
        for (int i = nfull + lane; i < n; i += 32) {
            int off = offs[i];
            float t = __fmul_rn(__fmaf_rn(__ldcs(ip + off), 0.5f, 0.5f), 255.0f);
            int bin = __float2int_rd(t) - 127;
            h[((bin << 5) & 0xF80) | hb_lane | (bin & 3)] += 1;
        }
        __syncwarp();

        // ---- reduce: lane l owns bins 4l..4l+3; sum byte cols of 32 lanes ----
        const uint32_t* hw = (const uint32_t*)h;
        uint32_t a02 = 0, a13 = 0;
        #pragma unroll
        for (int jj = 0; jj < 32; jj++) {
            int j = (jj + lane) & 31;
            uint32_t vv = hw[lane * 32 + j];
            a02 += vv & 0x00FF00FFu;
            a13 += (vv >> 8) & 0x00FF00FFu;
        }
        int h0 = (int)(a02 & 0xFFFFu), h2 = (int)(a02 >> 16);
        int h1 = (int)(a13 & 0xFFFFu), h3 = (int)(a13 >> 16);

        const int b0 = lane * 4;
        int sl  = h0 + h1 + h2 + h3;
        int sb  = h0 * b0 + h1 * (b0 + 1) + h2 * (b0 + 2) + h3 * (b0 + 3);
        int sb2 = h0 * b0 * b0 + h1 * (b0 + 1) * (b0 + 1)
                + h2 * (b0 + 2) * (b0 + 2) + h3 * (b0 + 3) * (b0 + 3);

        int sumb  = __reduce_add_sync(0xffffffffu, sb);
        int sumb2 = __reduce_add_sync(0xffffffffu, sb2);

        int sc = sl;
        #pragma unroll
        for (int d = 1; d < 32; d <<= 1) {
            int t2 = __shfl_up_sync(0xffffffffu, sc, d);
            if (lane >= d) sc += t2;
        }
        int cb = sc - sl;

        int k1 = (n - 1) >> 1, k2 = n >> 1;
        int c1 = 1 << 30, c2 = 1 << 30;
        {
            int t1 = k1 + 1;
            if (cb < t1 && t1 <= sc) {
                if      (cb + h0 >= t1)           c1 = b0;
                else if (cb + h0 + h1 >= t1)      c1 = b0 + 1;
                else if (cb + h0 + h1 + h2 >= t1) c1 = b0 + 2;
                else                              c1 = b0 + 3;
            }
            int t2r = k2 + 1;
            if (cb < t2r && t2r <= sc) {
                if      (cb + h0 >= t2r)           c2 = b0;
                else if (cb + h0 + h1 >= t2r)      c2 = b0 + 1;
                else if (cb + h0 + h1 + h2 >= t2r) c2 = b0 + 2;
                else                               c2 = b0 + 3;
            }
        }
        int m1 = __reduce_min_sync(0xffffffffu, c1);
        int m2 = __reduce_min_sync(0xffffffffu, c2);

        if (lane == 0) {
            double dn = (double)n;
            double mb = (double)sumb / dn;
            double mean = 127.0 + mb;
            double var = (double)sumb2 / dn - mb * mb;
            double sd = sqrt(var > 0.0 ? var : 0.0);
            double med = 127.0 + 0.5 * (double)(m1 + m2);
            int o = b * (NR * 9) + ring * 9 + c;
            out[o]     = (float)mean;
            out[o + 3] = (float)sd;
            out[o + 6] = (float)med;
        }
        __syncwarp();
    }
}

extern "C" void kernel_launch(void* const* d_in, const int* in_sizes, int n_in,
                              void* d_out, int out_size) {
    const float* img = (const float*)d_in[0];
    float* out = (float*)d_out;

    k_build<<<HH, 32>>>();
    k_main<<<1536, 128>>>(img, out);
}